// round 15
// baseline (speedup 1.0000x reference)
#include <cuda_runtime.h>
#include <cuda_bf16.h>
#include <cuda_fp16.h>
#include <math.h>
#include <stdint.h>

#define NROWS 32768
#define NBINS 9
#define MAXTILES 272
#define GEMM1_BLOCKS 544
#define ASTRA 264
#define BROWB 144
#define BBUF_SZ 18432

#define OFF_A    0
#define OFF_B    67584
#define OFF_SPW  104448
#define OFF_PBS  106496
#define OFF_PBS2 108544
#define OFF_SRED 110592
#define SMEM_SZ  112640

/* control block: [0,9) bincnt, [9,281) done, [281,285) sync */
#define CTRL_BINCNT 0
#define CTRL_DONE   9
#define CTRL_SYNC   281
#define CTRL_WORDS  285

__device__ __half g_buf0[(size_t)NROWS * 256];
__device__ float g_Wt0[(size_t)256 * 3072];
__device__ float g_Wt1[(size_t)256 * 3072];
__device__ __half g_Wp0[(size_t)NBINS * 256 * 1024];
__device__ __half g_Wp1[(size_t)NBINS * 256 * 1024];
__device__ float g_Pb0[NBINS * 4 * 256];
__device__ float g_Pb1[NBINS * 4 * 256];
__device__ float g_P2[NBINS * 4 * 256];
__device__ float g_Pb2[NBINS * 4];
__device__ int   g_perm[NROWS];
__device__ float g_tp[NROWS];
__device__ int   g_binstart[NBINS + 1];
__device__ int   g_cur[NBINS];
__device__ int   g_tilebin[MAXTILES];
__device__ int   g_tilem0[MAXTILES];
__device__ int   g_ntiles;
__device__ int   g_ctrl[CTRL_WORDS];

__device__ __forceinline__ void mma_f16(float* c, const uint32_t* a, uint32_t b0, uint32_t b1){
    asm volatile(
        "mma.sync.aligned.m16n8k16.row.col.f32.f16.f16.f32 "
        "{%0,%1,%2,%3},{%4,%5,%6,%7},{%8,%9},{%0,%1,%2,%3};"
        : "+f"(c[0]), "+f"(c[1]), "+f"(c[2]), "+f"(c[3])
        : "r"(a[0]), "r"(a[1]), "r"(a[2]), "r"(a[3]), "r"(b0), "r"(b1));
}
__device__ __forceinline__ uint32_t smem_u32(const void* p){
    uint32_t a;
    asm("{ .reg .u64 t; cvta.to.shared.u64 t, %1; cvt.u32.u64 %0, t; }" : "=r"(a) : "l"(p));
    return a;
}
__device__ __forceinline__ void ldsm4(uint32_t* r, uint32_t a){
    asm volatile("ldmatrix.sync.aligned.m8n8.x4.shared.b16 {%0,%1,%2,%3}, [%4];"
        : "=r"(r[0]), "=r"(r[1]), "=r"(r[2]), "=r"(r[3]) : "r"(a));
}
__device__ __forceinline__ void cpasync16(uint32_t dst, const void* src){
    asm volatile("cp.async.cg.shared.global [%0], [%1], 16;" :: "r"(dst), "l"(src) : "memory");
}
#define CP_COMMIT() asm volatile("cp.async.commit_group;" ::: "memory")
#define CP_WAIT0()  asm volatile("cp.async.wait_group 0;" ::: "memory")

__device__ __forceinline__ void spin_ge(int* addr, int target, int tid){
    if (tid == 0){ while (atomicAdd(addr, 0) < target) {} }
    __syncthreads();
}

// ---------------- ONE setup kernel ----------------
// blocks [0,64):      hist -> barrier -> (block0: scan) -> barrier -> scatter
// blocks [64,1600):   transpose W0/W1 -> bump sync[2]
// blocks [1600,2116): prep (weight blocks spin on sync[2]==1536)
__global__ void setup_all(const float* __restrict__ T,
                          const float* __restrict__ W0, const float* __restrict__ b0,
                          const float* __restrict__ W1, const float* __restrict__ b1,
                          const float* __restrict__ W2, const float* __restrict__ b2){
    const int bx = blockIdx.x, tid = threadIdx.x;
    if (bx < 64){
        const int gt = bx * 256 + tid;
        const int lane = tid & 31;
        for (int i = gt; i < NROWS; i += 64 * 256){
            int b = (int)(T[i] * 9.0f); b = b < 0 ? 0 : (b > 8 ? 8 : b);
            unsigned m = __match_any_sync(__activemask(), b);
            if (lane == __ffs(m) - 1) atomicAdd(&g_ctrl[CTRL_BINCNT + b], __popc(m));
        }
        __syncthreads();
        if (tid == 0){ __threadfence(); atomicAdd(&g_ctrl[CTRL_SYNC + 0], 1); }
        spin_ge(&g_ctrl[CTRL_SYNC + 0], 64, tid);
        if (bx == 0 && tid == 0){
            int off = 0, nt = 0;
            for (int b = 0; b < NBINS; b++){
                g_binstart[b] = off;
                g_cur[b] = off;
                int cnt = g_ctrl[CTRL_BINCNT + b];
                for (int ms = 0; ms < cnt; ms += 128){
                    g_tilebin[nt] = b; g_tilem0[nt] = off + ms; nt++;
                }
                off += cnt;
            }
            g_binstart[NBINS] = off;
            g_ntiles = nt;
            __threadfence();
            atomicExch(&g_ctrl[CTRL_SYNC + 1], 1);
        }
        spin_ge(&g_ctrl[CTRL_SYNC + 1], 1, tid);
        const int lane2 = tid & 31;
        for (int i = gt; i < NROWS; i += 64 * 256){
            float t = T[i];
            int b = (int)(t * 9.0f); b = b < 0 ? 0 : (b > 8 ? 8 : b);
            unsigned msk = __activemask();
            unsigned m = __match_any_sync(msk, b);
            int ldr = __ffs(m) - 1;
            int pre = __popc(m & ((1u << lane2) - 1u));
            int base = 0;
            if (lane2 == ldr) base = atomicAdd(&g_cur[b], __popc(m));
            base = __shfl_sync(msk, base, ldr);
            g_perm[base + pre] = i;
            g_tp[base + pre] = t;
        }
        return;
    }
    if (bx < 1600){
        __shared__ float tile[32][33];
        const int id = bx - 64;
        const int layer = id / 768;
        const int rem = id % 768;
        const int o0 = (rem & 7) * 32, k0 = (rem >> 3) * 32;
        const float* W = layer ? W1 : W0;
        float* Wt = layer ? g_Wt1 : g_Wt0;
        const int tx = tid & 31, ty = tid >> 5;
#pragma unroll
        for (int q = 0; q < 4; q++)
            tile[ty + q*8][tx] = W[(size_t)(k0 + ty + q*8) * 256 + o0 + tx];
        __syncthreads();
#pragma unroll
        for (int q = 0; q < 4; q++)
            Wt[(size_t)(o0 + ty + q*8) * 3072 + k0 + tx] = tile[tx][ty + q*8];
        __syncthreads();
        if (tid == 0){ __threadfence(); atomicAdd(&g_ctrl[CTRL_SYNC + 2], 1); }
        return;
    }
    const int id = bx - 1600;              // 0..515
    const int layer = id / 258;
    const int bx2 = id % 258;
    const int i = tid;
    if (bx2 == 257){
        if (layer) return;
        {
            const int o = i;
            float w[12];
#pragma unroll
            for (int s = 0; s < 12; s++) w[s] = W2[s*256 + o];
            float p[4] = {w[0], w[1], w[2], w[3]};
            for (int bin = 0; bin < NBINS; bin++){
                if (bin >= 1){
                    float k = (float)bin / 9.0f, ww = w[3 + bin];
                    p[3] += ww; p[2] -= 3.0f*k*ww; p[1] += 3.0f*k*k*ww; p[0] -= k*k*k*ww;
                }
#pragma unroll
                for (int j = 0; j < 4; j++) g_P2[(bin*4 + j)*256 + o] = p[j];
            }
        }
        if (i == 0){
            float w[12];
#pragma unroll
            for (int s = 0; s < 12; s++) w[s] = b2[s];
            float p[4] = {w[0], w[1], w[2], w[3]};
            for (int bin = 0; bin < NBINS; bin++){
                if (bin >= 1){
                    float k = (float)bin / 9.0f, ww = w[3 + bin];
                    p[3] += ww; p[2] -= 3.0f*k*ww; p[1] += 3.0f*k*k*ww; p[0] -= k*k*k*ww;
                }
#pragma unroll
                for (int j = 0; j < 4; j++) g_Pb2[bin*4 + j] = p[j];
            }
        }
        return;
    }
    if (bx2 == 256){
        const float* Bv = layer ? b1 : b0;
        float* Pb = layer ? g_Pb1 : g_Pb0;
        const int o = i;
        float w[12];
#pragma unroll
        for (int s = 0; s < 12; s++) w[s] = Bv[s*256 + o];
        float p[4] = {w[0], w[1], w[2], w[3]};
        for (int bin = 0; bin < NBINS; bin++){
            if (bin >= 1){
                float k = (float)bin / 9.0f, ww = w[3 + bin];
                p[3] += ww; p[2] -= 3.0f*k*ww; p[1] += 3.0f*k*k*ww; p[0] -= k*k*k*ww;
            }
#pragma unroll
            for (int j = 0; j < 4; j++) Pb[(bin*4 + j)*256 + o] = p[j];
        }
        return;
    }
    // weight prep: needs transpose done
    spin_ge(&g_ctrl[CTRL_SYNC + 2], 1536, tid);
    const float* Wt = layer ? g_Wt1 : g_Wt0;
    __half* Hi = layer ? g_Wp1 : g_Wp0;
    const int o = bx2;
    float w[12];
#pragma unroll
    for (int s = 0; s < 12; s++) w[s] = Wt[(size_t)o * 3072 + s*256 + i];
    float p[4] = {w[0], w[1], w[2], w[3]};
    for (int bin = 0; bin < NBINS; bin++){
        if (bin >= 1){
            float k = (float)bin / 9.0f, ww = w[3 + bin];
            p[3] += ww; p[2] -= 3.0f*k*ww; p[1] += 3.0f*k*k*ww; p[0] -= k*k*k*ww;
        }
#pragma unroll
        for (int j = 0; j < 4; j++)
            Hi[((size_t)bin*256 + o)*1024 + j*256 + i] = __float2half_rn(p[j]);
    }
}

// ---------------- fused dual-layer GEMM ----------------
__global__ void __launch_bounds__(256, 2) vc_fused(
    const float* __restrict__ X, float* __restrict__ Out)
{
    const int layer = (blockIdx.x >= GEMM1_BLOCKS) ? 1 : 0;
    const int bb = blockIdx.x - layer * GEMM1_BLOCKS;
    const int tile = bb >> 1;
    if (tile >= g_ntiles) return;
    const int n0 = (bb & 1) * 128;

    extern __shared__ __align__(16) char smem[];
    __half* Ah = (__half*)(smem + OFF_A);
    float* spw  = (float*)(smem + OFF_SPW);
    float* pbs  = (float*)(smem + OFF_PBS);
    float* pbs2 = (float*)(smem + OFF_PBS2);
    float* sred = (float*)(smem + OFF_SRED);

    const int tid = threadIdx.x, wid = tid >> 5, lane = tid & 31;
    const int bin = g_tilebin[tile];
    const int m0  = g_tilem0[tile];
    const int rows = min(128, g_binstart[bin + 1] - m0);

    const __half* WHi = (layer ? g_Wp1 : g_Wp0);
    const float*  Pb  = (layer ? g_Pb1 : g_Pb0);

    if (tid < 128){
        float t = (tid < rows) ? g_tp[m0 + tid] : 0.0f;
        float e = (tid < rows) ? 1.0f : 0.0f;
        spw[tid*4+0] = e; spw[tid*4+1] = e*t; spw[tid*4+2] = e*t*t; spw[tid*4+3] = e*t*t*t;
    }
#pragma unroll
    for (int q = 0; q < 2; q++){
        int idx = q*256 + tid;
        pbs[idx] = Pb[(bin*4 + (idx >> 7))*256 + n0 + (idx & 127)];
        if (layer) pbs2[idx] = g_P2[(bin*4 + (idx >> 7))*256 + n0 + (idx & 127)];
    }

    const size_t wbase = (size_t)bin * 256 * 1024;
    const uint32_t sBbase = smem_u32(smem + OFF_B);
#pragma unroll
    for (int it = 0; it < 4; it++){
        int idx = it*256 + tid, o = idx >> 3, q = idx & 7;
        cpasync16(sBbase + (uint32_t)(o*BROWB + q*16),
                  WHi + wbase + (size_t)(n0 + o)*1024 + 3*256 + q*8);
    }
    CP_COMMIT();

    const int r = tid >> 1, h = tid & 1;
    const int rs = min(r, rows - 1);
    const uint32_t sAbase = smem_u32(Ah);
    if (!layer){
        const float* xrow = X + (size_t)g_perm[m0 + rs] * 256 + h*128;
#pragma unroll
        for (int q8 = 0; q8 < 16; q8++){
            float4 a = *(const float4*)(xrow + q8*8);
            float4 b = *(const float4*)(xrow + q8*8 + 4);
            __half2 h0 = __floats2half2_rn(a.x, a.y), h1 = __floats2half2_rn(a.z, a.w);
            __half2 h2 = __floats2half2_rn(b.x, b.y), h3 = __floats2half2_rn(b.z, b.w);
            *(uint4*)((char*)Ah + r*(ASTRA*2) + h*256 + q8*16) =
                make_uint4(*(uint32_t*)&h0, *(uint32_t*)&h1, *(uint32_t*)&h2, *(uint32_t*)&h3);
        }
    } else {
        if (tid == 0){
            while (atomicAdd(&g_ctrl[CTRL_DONE + tile], 0) < 2) {}
        }
        __syncthreads();
        const __half* xrow = g_buf0 + (size_t)(m0 + rs) * 256 + h*128;
#pragma unroll
        for (int q8 = 0; q8 < 16; q8++)
            cpasync16(sAbase + (uint32_t)(r*(ASTRA*2) + h*256 + q8*16), xrow + q8*8);
        CP_COMMIT();
    }
    __syncthreads();

    const int wm = (wid >> 1) * 32, wn = (wid & 1) * 64;
    const int lr = lane >> 2, lk = lane & 3;
    const uint32_t aAddrBase = sAbase
        + (uint32_t)(wm + (lane & 15))*(ASTRA*2) + (uint32_t)(lane >> 4)*16;
    const uint32_t bAddrBase = sBbase
        + (uint32_t)(wn + (lane >> 4)*8 + (lane & 7))*BROWB + (uint32_t)((lane >> 3) & 1)*16;
    float tA[2][2];
#pragma unroll
    for (int mt = 0; mt < 2; mt++){
        tA[mt][0] = spw[(wm + mt*16 + lr)*4 + 1];
        tA[mt][1] = spw[(wm + mt*16 + lr + 8)*4 + 1];
    }

    float acc[2][8][4];
#pragma unroll
    for (int a = 0; a < 2; a++)
#pragma unroll
        for (int b = 0; b < 8; b++)
#pragma unroll
            for (int c = 0; c < 4; c++) acc[a][b][c] = 0.0f;

    for (int s = 0; s < 16; s++){
        const int buf = s & 1;
        const int ic = s & 3;
        CP_WAIT0();
        __syncthreads();
        // ---- initial fragment batch (issue ldsm latency first) ----
        uint32_t af[2][8], bf[3][4];
        ldsm4(&af[0][0], aAddrBase + ic*128);
        ldsm4(&af[0][4], aAddrBase + 16*(ASTRA*2) + ic*128);
        ldsm4(&af[1][0], aAddrBase + ic*128 + 32);
        ldsm4(&af[1][4], aAddrBase + 16*(ASTRA*2) + ic*128 + 32);
        const uint32_t bSlab = bAddrBase + buf*BBUF_SZ;
        ldsm4(bf[0], bSlab);                       // frag 0 (kk0,np0)
        ldsm4(bf[1], bSlab + 16*BROWB);            // frag 1 (kk0,np1)
        // ---- next-slab cp.async ----
        if (s < 15){
            const int sn = s + 1;
            const int koff = (3 - (sn >> 2))*256 + (sn & 3)*64;
#pragma unroll
            for (int it = 0; it < 4; it++){
                int idx = it*256 + tid, o = idx >> 3, q = idx & 7;
                cpasync16(sBbase + (uint32_t)((buf ^ 1)*BBUF_SZ + o*BROWB + q*16),
                          WHi + wbase + (size_t)(n0 + o)*1024 + koff + q*8);
            }
            CP_COMMIT();
        }
#pragma unroll
        for (int idx = 0; idx < 16; idx++){
            const int kk = idx >> 2, np = idx & 3, cur = idx % 3;
            if (idx < 14){
                const int nidx = idx + 2;
                ldsm4(bf[nidx % 3], bSlab + (nidx & 3)*16*BROWB + (nidx >> 2)*32);
            }
            if (np == 0 && kk >= 1 && kk < 3){
                ldsm4(&af[(kk + 1) & 1][0], aAddrBase + ic*128 + (kk+1)*32);
                ldsm4(&af[(kk + 1) & 1][4], aAddrBase + 16*(ASTRA*2) + ic*128 + (kk+1)*32);
            }
            const uint32_t* a0 = af[kk & 1];
            mma_f16(acc[0][np*2 + 0], a0,     bf[cur][0], bf[cur][1]);
            mma_f16(acc[0][np*2 + 1], a0,     bf[cur][2], bf[cur][3]);
            mma_f16(acc[1][np*2 + 0], a0 + 4, bf[cur][0], bf[cur][1]);
            mma_f16(acc[1][np*2 + 1], a0 + 4, bf[cur][2], bf[cur][3]);
        }
        if ((s & 3) == 3 && s < 15){
#pragma unroll
            for (int mt = 0; mt < 2; mt++)
#pragma unroll
                for (int nt = 0; nt < 8; nt++){
                    acc[mt][nt][0] *= tA[mt][0];
                    acc[mt][nt][1] *= tA[mt][0];
                    acc[mt][nt][2] *= tA[mt][1];
                    acc[mt][nt][3] *= tA[mt][1];
                }
        }
    }

    if (!layer){
#pragma unroll
        for (int mt = 0; mt < 2; mt++){
#pragma unroll
            for (int half = 0; half < 2; half++){
                int rr = wm + mt*16 + lr + half*8;
                if (rr >= rows) continue;
                float pw0 = spw[rr*4+0], pw1 = spw[rr*4+1], pw2 = spw[rr*4+2], pw3 = spw[rr*4+3];
                __half* yp = g_buf0 + (size_t)(m0 + rr) * 256 + n0;
#pragma unroll
                for (int nt = 0; nt < 8; nt++){
                    int col = wn + nt*8 + lk*2;
                    float b0 = pw0*pbs[col]   + pw1*pbs[128+col]   + pw2*pbs[256+col]   + pw3*pbs[384+col];
                    float b1 = pw0*pbs[col+1] + pw1*pbs[128+col+1] + pw2*pbs[256+col+1] + pw3*pbs[384+col+1];
                    float v0 = fmaxf(acc[mt][nt][half*2 + 0] + b0, 0.0f);
                    float v1 = fmaxf(acc[mt][nt][half*2 + 1] + b1, 0.0f);
                    *(__half2*)(yp + col) = __floats2half2_rn(v0, v1);
                }
            }
        }
        __threadfence();
        __syncthreads();
        if (tid == 0) atomicAdd(&g_ctrl[CTRL_DONE + tile], 1);
    } else {
#pragma unroll
        for (int q = 0; q < 2; q++) sred[q*256 + tid] = 0.0f;
        __syncthreads();
#pragma unroll
        for (int mt = 0; mt < 2; mt++){
#pragma unroll
            for (int half = 0; half < 2; half++){
                int rr = wm + mt*16 + lr + half*8;
                float pw0 = spw[rr*4+0], pw1 = spw[rr*4+1], pw2 = spw[rr*4+2], pw3 = spw[rr*4+3];
                float s0 = 0.f, s1 = 0.f, s2 = 0.f, s3 = 0.f;
#pragma unroll
                for (int nt = 0; nt < 8; nt++){
                    int col = wn + nt*8 + lk*2;
                    float b0 = pw0*pbs[col]   + pw1*pbs[128+col]   + pw2*pbs[256+col]   + pw3*pbs[384+col];
                    float b1 = pw0*pbs[col+1] + pw1*pbs[128+col+1] + pw2*pbs[256+col+1] + pw3*pbs[384+col+1];
                    float v0 = fmaxf(acc[mt][nt][half*2 + 0] + b0, 0.0f);
                    float v1 = fmaxf(acc[mt][nt][half*2 + 1] + b1, 0.0f);
                    s0 += v0*pbs2[col]     + v1*pbs2[col+1];
                    s1 += v0*pbs2[128+col] + v1*pbs2[128+col+1];
                    s2 += v0*pbs2[256+col] + v1*pbs2[256+col+1];
                    s3 += v0*pbs2[384+col] + v1*pbs2[384+col+1];
                }
#pragma unroll
                for (int off = 1; off <= 2; off <<= 1){
                    s0 += __shfl_xor_sync(0xffffffffu, s0, off);
                    s1 += __shfl_xor_sync(0xffffffffu, s1, off);
                    s2 += __shfl_xor_sync(0xffffffffu, s2, off);
                    s3 += __shfl_xor_sync(0xffffffffu, s3, off);
                }
                if (lk == 0){
                    atomicAdd(&sred[rr*4 + 0], s0);
                    atomicAdd(&sred[rr*4 + 1], s1);
                    atomicAdd(&sred[rr*4 + 2], s2);
                    atomicAdd(&sred[rr*4 + 3], s3);
                }
            }
        }
        __syncthreads();
        if (tid < rows){
            float pw0 = spw[tid*4+0], pw1 = spw[tid*4+1], pw2 = spw[tid*4+2], pw3 = spw[tid*4+3];
            float rsl = pw0*sred[tid*4+0] + pw1*sred[tid*4+1]
                      + pw2*sred[tid*4+2] + pw3*sred[tid*4+3];
            if (n0 == 0)
                rsl += pw0*g_Pb2[bin*4+0] + pw1*g_Pb2[bin*4+1]
                     + pw2*g_Pb2[bin*4+2] + pw3*g_Pb2[bin*4+3];
            atomicAdd(Out + g_perm[m0 + tid], rsl);
        }
    }
}

extern "C" void kernel_launch(void* const* d_in, const int* in_sizes, int n_in,
                              void* d_out, int out_size)
{
    const float* T  = (const float*)d_in[0];
    const float* X  = (const float*)d_in[1];
    const float* W0 = (const float*)d_in[2];
    const float* b0 = (const float*)d_in[3];
    const float* W1 = (const float*)d_in[4];
    const float* b1 = (const float*)d_in[5];
    const float* W2 = (const float*)d_in[6];
    const float* b2 = (const float*)d_in[7];
    float* out = (float*)d_out;

    int* ctrl;
    cudaGetSymbolAddress((void**)&ctrl, g_ctrl);

    cudaFuncSetAttribute(vc_fused, cudaFuncAttributeMaxDynamicSharedMemorySize, SMEM_SZ);

    cudaMemsetAsync(ctrl, 0, CTRL_WORDS * sizeof(int), 0);
    cudaMemsetAsync(out, 0, NROWS * sizeof(float), 0);
    setup_all<<<2116, 256>>>(T, W0, b0, W1, b1, W2, b2);
    vc_fused<<<2 * GEMM1_BLOCKS, 256, SMEM_SZ>>>(X, out);
}

// round 16
// speedup vs baseline: 1.0243x; 1.0243x over previous
#include <cuda_runtime.h>
#include <cuda_bf16.h>
#include <cuda_fp16.h>
#include <math.h>
#include <stdint.h>

#define NROWS 32768
#define NBINS 9
#define MAXTILES 272
#define GEMM1_BLOCKS 544
#define ASTRA 264
#define BROWB 144
#define BBUF_SZ 18432

#define OFF_A    0
#define OFF_B    67584
#define OFF_SPW  104448
#define OFF_PBS  106496
#define OFF_PBS2 108544
#define OFF_SRED 110592
#define SMEM_SZ  112640

/* control block: [0,9) bincnt, [9,281) done, [281,285) sync */
#define CTRL_BINCNT 0
#define CTRL_DONE   9
#define CTRL_SYNC   281
#define CTRL_WORDS  285

__device__ __half g_buf0[(size_t)NROWS * 256];
__device__ float g_Wt0[(size_t)256 * 3072];
__device__ float g_Wt1[(size_t)256 * 3072];
__device__ __half g_Wp0[(size_t)NBINS * 256 * 1024];
__device__ __half g_Wp1[(size_t)NBINS * 256 * 1024];
__device__ float g_Pb0[NBINS * 4 * 256];
__device__ float g_Pb1[NBINS * 4 * 256];
__device__ float g_P2[NBINS * 4 * 256];
__device__ float g_Pb2[NBINS * 4];
__device__ int   g_perm[NROWS];
__device__ float g_tp[NROWS];
__device__ int   g_binstart[NBINS + 1];
__device__ int   g_cur[NBINS];
__device__ int   g_tilebin[MAXTILES];
__device__ int   g_tilem0[MAXTILES];
__device__ int   g_ntiles;
__device__ int   g_ctrl[CTRL_WORDS];

__device__ __forceinline__ void mma_f16(float* c, const uint32_t* a, uint32_t b0, uint32_t b1){
    asm volatile(
        "mma.sync.aligned.m16n8k16.row.col.f32.f16.f16.f32 "
        "{%0,%1,%2,%3},{%4,%5,%6,%7},{%8,%9},{%0,%1,%2,%3};"
        : "+f"(c[0]), "+f"(c[1]), "+f"(c[2]), "+f"(c[3])
        : "r"(a[0]), "r"(a[1]), "r"(a[2]), "r"(a[3]), "r"(b0), "r"(b1));
}
__device__ __forceinline__ uint32_t smem_u32(const void* p){
    uint32_t a;
    asm("{ .reg .u64 t; cvta.to.shared.u64 t, %1; cvt.u32.u64 %0, t; }" : "=r"(a) : "l"(p));
    return a;
}
__device__ __forceinline__ void ldsm4(uint32_t* r, uint32_t a){
    asm volatile("ldmatrix.sync.aligned.m8n8.x4.shared.b16 {%0,%1,%2,%3}, [%4];"
        : "=r"(r[0]), "=r"(r[1]), "=r"(r[2]), "=r"(r[3]) : "r"(a));
}
__device__ __forceinline__ void cpasync16(uint32_t dst, const void* src){
    asm volatile("cp.async.cg.shared.global [%0], [%1], 16;" :: "r"(dst), "l"(src) : "memory");
}
#define CP_COMMIT() asm volatile("cp.async.commit_group;" ::: "memory")
#define CP_WAIT0()  asm volatile("cp.async.wait_group 0;" ::: "memory")

__device__ __forceinline__ void spin_ge(int* addr, int target, int tid){
    if (tid == 0){ while (atomicAdd(addr, 0) < target) {} }
    __syncthreads();
}

// ---------------- ONE setup kernel (R15, measured good) ----------------
__global__ void setup_all(const float* __restrict__ T,
                          const float* __restrict__ W0, const float* __restrict__ b0,
                          const float* __restrict__ W1, const float* __restrict__ b1,
                          const float* __restrict__ W2, const float* __restrict__ b2){
    const int bx = blockIdx.x, tid = threadIdx.x;
    if (bx < 64){
        const int gt = bx * 256 + tid;
        const int lane = tid & 31;
        for (int i = gt; i < NROWS; i += 64 * 256){
            int b = (int)(T[i] * 9.0f); b = b < 0 ? 0 : (b > 8 ? 8 : b);
            unsigned m = __match_any_sync(__activemask(), b);
            if (lane == __ffs(m) - 1) atomicAdd(&g_ctrl[CTRL_BINCNT + b], __popc(m));
        }
        __syncthreads();
        if (tid == 0){ __threadfence(); atomicAdd(&g_ctrl[CTRL_SYNC + 0], 1); }
        spin_ge(&g_ctrl[CTRL_SYNC + 0], 64, tid);
        if (bx == 0 && tid == 0){
            int off = 0, nt = 0;
            for (int b = 0; b < NBINS; b++){
                g_binstart[b] = off;
                g_cur[b] = off;
                int cnt = g_ctrl[CTRL_BINCNT + b];
                for (int ms = 0; ms < cnt; ms += 128){
                    g_tilebin[nt] = b; g_tilem0[nt] = off + ms; nt++;
                }
                off += cnt;
            }
            g_binstart[NBINS] = off;
            g_ntiles = nt;
            __threadfence();
            atomicExch(&g_ctrl[CTRL_SYNC + 1], 1);
        }
        spin_ge(&g_ctrl[CTRL_SYNC + 1], 1, tid);
        const int lane2 = tid & 31;
        for (int i = gt; i < NROWS; i += 64 * 256){
            float t = T[i];
            int b = (int)(t * 9.0f); b = b < 0 ? 0 : (b > 8 ? 8 : b);
            unsigned msk = __activemask();
            unsigned m = __match_any_sync(msk, b);
            int ldr = __ffs(m) - 1;
            int pre = __popc(m & ((1u << lane2) - 1u));
            int base = 0;
            if (lane2 == ldr) base = atomicAdd(&g_cur[b], __popc(m));
            base = __shfl_sync(msk, base, ldr);
            g_perm[base + pre] = i;
            g_tp[base + pre] = t;
        }
        return;
    }
    if (bx < 1600){
        __shared__ float tile[32][33];
        const int id = bx - 64;
        const int layer = id / 768;
        const int rem = id % 768;
        const int o0 = (rem & 7) * 32, k0 = (rem >> 3) * 32;
        const float* W = layer ? W1 : W0;
        float* Wt = layer ? g_Wt1 : g_Wt0;
        const int tx = tid & 31, ty = tid >> 5;
#pragma unroll
        for (int q = 0; q < 4; q++)
            tile[ty + q*8][tx] = W[(size_t)(k0 + ty + q*8) * 256 + o0 + tx];
        __syncthreads();
#pragma unroll
        for (int q = 0; q < 4; q++)
            Wt[(size_t)(o0 + ty + q*8) * 3072 + k0 + tx] = tile[tx][ty + q*8];
        __syncthreads();
        if (tid == 0){ __threadfence(); atomicAdd(&g_ctrl[CTRL_SYNC + 2], 1); }
        return;
    }
    const int id = bx - 1600;              // 0..515
    const int layer = id / 258;
    const int bx2 = id % 258;
    const int i = tid;
    if (bx2 == 257){
        if (layer) return;
        {
            const int o = i;
            float w[12];
#pragma unroll
            for (int s = 0; s < 12; s++) w[s] = W2[s*256 + o];
            float p[4] = {w[0], w[1], w[2], w[3]};
            for (int bin = 0; bin < NBINS; bin++){
                if (bin >= 1){
                    float k = (float)bin / 9.0f, ww = w[3 + bin];
                    p[3] += ww; p[2] -= 3.0f*k*ww; p[1] += 3.0f*k*k*ww; p[0] -= k*k*k*ww;
                }
#pragma unroll
                for (int j = 0; j < 4; j++) g_P2[(bin*4 + j)*256 + o] = p[j];
            }
        }
        if (i == 0){
            float w[12];
#pragma unroll
            for (int s = 0; s < 12; s++) w[s] = b2[s];
            float p[4] = {w[0], w[1], w[2], w[3]};
            for (int bin = 0; bin < NBINS; bin++){
                if (bin >= 1){
                    float k = (float)bin / 9.0f, ww = w[3 + bin];
                    p[3] += ww; p[2] -= 3.0f*k*ww; p[1] += 3.0f*k*k*ww; p[0] -= k*k*k*ww;
                }
#pragma unroll
                for (int j = 0; j < 4; j++) g_Pb2[bin*4 + j] = p[j];
            }
        }
        return;
    }
    if (bx2 == 256){
        const float* Bv = layer ? b1 : b0;
        float* Pb = layer ? g_Pb1 : g_Pb0;
        const int o = i;
        float w[12];
#pragma unroll
        for (int s = 0; s < 12; s++) w[s] = Bv[s*256 + o];
        float p[4] = {w[0], w[1], w[2], w[3]};
        for (int bin = 0; bin < NBINS; bin++){
            if (bin >= 1){
                float k = (float)bin / 9.0f, ww = w[3 + bin];
                p[3] += ww; p[2] -= 3.0f*k*ww; p[1] += 3.0f*k*k*ww; p[0] -= k*k*k*ww;
            }
#pragma unroll
            for (int j = 0; j < 4; j++) Pb[(bin*4 + j)*256 + o] = p[j];
        }
        return;
    }
    spin_ge(&g_ctrl[CTRL_SYNC + 2], 1536, tid);
    const float* Wt = layer ? g_Wt1 : g_Wt0;
    __half* Hi = layer ? g_Wp1 : g_Wp0;
    const int o = bx2;
    float w[12];
#pragma unroll
    for (int s = 0; s < 12; s++) w[s] = Wt[(size_t)o * 3072 + s*256 + i];
    float p[4] = {w[0], w[1], w[2], w[3]};
    for (int bin = 0; bin < NBINS; bin++){
        if (bin >= 1){
            float k = (float)bin / 9.0f, ww = w[3 + bin];
            p[3] += ww; p[2] -= 3.0f*k*ww; p[1] += 3.0f*k*k*ww; p[0] -= k*k*k*ww;
        }
#pragma unroll
        for (int j = 0; j < 4; j++)
            Hi[((size_t)bin*256 + o)*1024 + j*256 + i] = __float2half_rn(p[j]);
    }
}

// ---------------- fused dual-layer GEMM (R14 inner loop, measured best) ----------------
__global__ void __launch_bounds__(256, 2) vc_fused(
    const float* __restrict__ X, float* __restrict__ Out)
{
    const int layer = (blockIdx.x >= GEMM1_BLOCKS) ? 1 : 0;
    const int bb = blockIdx.x - layer * GEMM1_BLOCKS;
    const int tile = bb >> 1;
    if (tile >= g_ntiles) return;
    const int n0 = (bb & 1) * 128;

    extern __shared__ __align__(16) char smem[];
    __half* Ah = (__half*)(smem + OFF_A);
    float* spw  = (float*)(smem + OFF_SPW);
    float* pbs  = (float*)(smem + OFF_PBS);
    float* pbs2 = (float*)(smem + OFF_PBS2);
    float* sred = (float*)(smem + OFF_SRED);

    const int tid = threadIdx.x, wid = tid >> 5, lane = tid & 31;
    const int bin = g_tilebin[tile];
    const int m0  = g_tilem0[tile];
    const int rows = min(128, g_binstart[bin + 1] - m0);

    const __half* WHi = (layer ? g_Wp1 : g_Wp0);
    const float*  Pb  = (layer ? g_Pb1 : g_Pb0);

    if (tid < 128){
        float t = (tid < rows) ? g_tp[m0 + tid] : 0.0f;
        float e = (tid < rows) ? 1.0f : 0.0f;
        spw[tid*4+0] = e; spw[tid*4+1] = e*t; spw[tid*4+2] = e*t*t; spw[tid*4+3] = e*t*t*t;
    }
#pragma unroll
    for (int q = 0; q < 2; q++){
        int idx = q*256 + tid;
        pbs[idx] = Pb[(bin*4 + (idx >> 7))*256 + n0 + (idx & 127)];
        if (layer) pbs2[idx] = g_P2[(bin*4 + (idx >> 7))*256 + n0 + (idx & 127)];
    }

    const size_t wbase = (size_t)bin * 256 * 1024;
    const uint32_t sBbase = smem_u32(smem + OFF_B);
#pragma unroll
    for (int it = 0; it < 4; it++){
        int idx = it*256 + tid, o = idx >> 3, q = idx & 7;
        cpasync16(sBbase + (uint32_t)(o*BROWB + q*16),
                  WHi + wbase + (size_t)(n0 + o)*1024 + 3*256 + q*8);
    }
    CP_COMMIT();

    const int r = tid >> 1, h = tid & 1;
    const int rs = min(r, rows - 1);
    const uint32_t sAbase = smem_u32(Ah);
    if (!layer){
        const float* xrow = X + (size_t)g_perm[m0 + rs] * 256 + h*128;
#pragma unroll
        for (int q8 = 0; q8 < 16; q8++){
            float4 a = *(const float4*)(xrow + q8*8);
            float4 b = *(const float4*)(xrow + q8*8 + 4);
            __half2 h0 = __floats2half2_rn(a.x, a.y), h1 = __floats2half2_rn(a.z, a.w);
            __half2 h2 = __floats2half2_rn(b.x, b.y), h3 = __floats2half2_rn(b.z, b.w);
            *(uint4*)((char*)Ah + r*(ASTRA*2) + h*256 + q8*16) =
                make_uint4(*(uint32_t*)&h0, *(uint32_t*)&h1, *(uint32_t*)&h2, *(uint32_t*)&h3);
        }
    } else {
        if (tid == 0){
            while (atomicAdd(&g_ctrl[CTRL_DONE + tile], 0) < 2) {}
        }
        __syncthreads();
        const __half* xrow = g_buf0 + (size_t)(m0 + rs) * 256 + h*128;
#pragma unroll
        for (int q8 = 0; q8 < 16; q8++)
            cpasync16(sAbase + (uint32_t)(r*(ASTRA*2) + h*256 + q8*16), xrow + q8*8);
        CP_COMMIT();
    }
    __syncthreads();

    const int wm = (wid >> 1) * 32, wn = (wid & 1) * 64;
    const int lr = lane >> 2, lk = lane & 3;
    const uint32_t aAddrBase = sAbase
        + (uint32_t)(wm + (lane & 15))*(ASTRA*2) + (uint32_t)(lane >> 4)*16;
    const uint32_t bAddrBase = sBbase
        + (uint32_t)(wn + (lane >> 4)*8 + (lane & 7))*BROWB + (uint32_t)((lane >> 3) & 1)*16;
    float tA[2][2];
#pragma unroll
    for (int mt = 0; mt < 2; mt++){
        tA[mt][0] = spw[(wm + mt*16 + lr)*4 + 1];
        tA[mt][1] = spw[(wm + mt*16 + lr + 8)*4 + 1];
    }

    float acc[2][8][4];
#pragma unroll
    for (int a = 0; a < 2; a++)
#pragma unroll
        for (int b = 0; b < 8; b++)
#pragma unroll
            for (int c = 0; c < 4; c++) acc[a][b][c] = 0.0f;

    for (int s = 0; s < 16; s++){
        const int buf = s & 1;
        const int ic = s & 3;
        CP_WAIT0();
        __syncthreads();
        if (s < 15){
            const int sn = s + 1;
            const int koff = (3 - (sn >> 2))*256 + (sn & 3)*64;
#pragma unroll
            for (int it = 0; it < 4; it++){
                int idx = it*256 + tid, o = idx >> 3, q = idx & 7;
                cpasync16(sBbase + (uint32_t)((buf ^ 1)*BBUF_SZ + o*BROWB + q*16),
                          WHi + wbase + (size_t)(n0 + o)*1024 + koff + q*8);
            }
            CP_COMMIT();
        }
        uint32_t af[2][8], bf[2][4];
        ldsm4(&af[0][0], aAddrBase + ic*128);
        ldsm4(&af[0][4], aAddrBase + 16*(ASTRA*2) + ic*128);
        ldsm4(&af[1][0], aAddrBase + ic*128 + 32);
        ldsm4(&af[1][4], aAddrBase + 16*(ASTRA*2) + ic*128 + 32);
        const uint32_t bSlab = bAddrBase + buf*BBUF_SZ;
        ldsm4(bf[0], bSlab);
#pragma unroll
        for (int idx = 0; idx < 16; idx++){
            const int kk = idx >> 2, np = idx & 3, cur = idx & 1;
            if (idx < 15){
                const int nidx = idx + 1;
                ldsm4(bf[cur ^ 1], bSlab + (nidx & 3)*16*BROWB + (nidx >> 2)*32);
            }
            if (np == 0 && kk >= 1 && kk < 3){
                ldsm4(&af[(kk + 1) & 1][0], aAddrBase + ic*128 + (kk+1)*32);
                ldsm4(&af[(kk + 1) & 1][4], aAddrBase + 16*(ASTRA*2) + ic*128 + (kk+1)*32);
            }
            const uint32_t* a0 = af[kk & 1];
            mma_f16(acc[0][np*2 + 0], a0,     bf[cur][0], bf[cur][1]);
            mma_f16(acc[0][np*2 + 1], a0,     bf[cur][2], bf[cur][3]);
            mma_f16(acc[1][np*2 + 0], a0 + 4, bf[cur][0], bf[cur][1]);
            mma_f16(acc[1][np*2 + 1], a0 + 4, bf[cur][2], bf[cur][3]);
        }
        if ((s & 3) == 3 && s < 15){
#pragma unroll
            for (int mt = 0; mt < 2; mt++)
#pragma unroll
                for (int nt = 0; nt < 8; nt++){
                    acc[mt][nt][0] *= tA[mt][0];
                    acc[mt][nt][1] *= tA[mt][0];
                    acc[mt][nt][2] *= tA[mt][1];
                    acc[mt][nt][3] *= tA[mt][1];
                }
        }
    }

    if (!layer){
#pragma unroll
        for (int mt = 0; mt < 2; mt++){
#pragma unroll
            for (int half = 0; half < 2; half++){
                int rr = wm + mt*16 + lr + half*8;
                if (rr >= rows) continue;
                float pw0 = spw[rr*4+0], pw1 = spw[rr*4+1], pw2 = spw[rr*4+2], pw3 = spw[rr*4+3];
                __half* yp = g_buf0 + (size_t)(m0 + rr) * 256 + n0;
#pragma unroll
                for (int nt = 0; nt < 8; nt++){
                    int col = wn + nt*8 + lk*2;
                    float b0 = pw0*pbs[col]   + pw1*pbs[128+col]   + pw2*pbs[256+col]   + pw3*pbs[384+col];
                    float b1 = pw0*pbs[col+1] + pw1*pbs[128+col+1] + pw2*pbs[256+col+1] + pw3*pbs[384+col+1];
                    float v0 = fmaxf(acc[mt][nt][half*2 + 0] + b0, 0.0f);
                    float v1 = fmaxf(acc[mt][nt][half*2 + 1] + b1, 0.0f);
                    *(__half2*)(yp + col) = __floats2half2_rn(v0, v1);
                }
            }
        }
        __threadfence();
        __syncthreads();
        if (tid == 0) atomicAdd(&g_ctrl[CTRL_DONE + tile], 1);
    } else {
#pragma unroll
        for (int q = 0; q < 2; q++) sred[q*256 + tid] = 0.0f;
        __syncthreads();
#pragma unroll
        for (int mt = 0; mt < 2; mt++){
#pragma unroll
            for (int half = 0; half < 2; half++){
                int rr = wm + mt*16 + lr + half*8;
                float pw0 = spw[rr*4+0], pw1 = spw[rr*4+1], pw2 = spw[rr*4+2], pw3 = spw[rr*4+3];
                float s0 = 0.f, s1 = 0.f, s2 = 0.f, s3 = 0.f;
#pragma unroll
                for (int nt = 0; nt < 8; nt++){
                    int col = wn + nt*8 + lk*2;
                    float b0 = pw0*pbs[col]   + pw1*pbs[128+col]   + pw2*pbs[256+col]   + pw3*pbs[384+col];
                    float b1 = pw0*pbs[col+1] + pw1*pbs[128+col+1] + pw2*pbs[256+col+1] + pw3*pbs[384+col+1];
                    float v0 = fmaxf(acc[mt][nt][half*2 + 0] + b0, 0.0f);
                    float v1 = fmaxf(acc[mt][nt][half*2 + 1] + b1, 0.0f);
                    s0 += v0*pbs2[col]     + v1*pbs2[col+1];
                    s1 += v0*pbs2[128+col] + v1*pbs2[128+col+1];
                    s2 += v0*pbs2[256+col] + v1*pbs2[256+col+1];
                    s3 += v0*pbs2[384+col] + v1*pbs2[384+col+1];
                }
#pragma unroll
                for (int off = 1; off <= 2; off <<= 1){
                    s0 += __shfl_xor_sync(0xffffffffu, s0, off);
                    s1 += __shfl_xor_sync(0xffffffffu, s1, off);
                    s2 += __shfl_xor_sync(0xffffffffu, s2, off);
                    s3 += __shfl_xor_sync(0xffffffffu, s3, off);
                }
                if (lk == 0){
                    atomicAdd(&sred[rr*4 + 0], s0);
                    atomicAdd(&sred[rr*4 + 1], s1);
                    atomicAdd(&sred[rr*4 + 2], s2);
                    atomicAdd(&sred[rr*4 + 3], s3);
                }
            }
        }
        __syncthreads();
        if (tid < rows){
            float pw0 = spw[tid*4+0], pw1 = spw[tid*4+1], pw2 = spw[tid*4+2], pw3 = spw[tid*4+3];
            float rsl = pw0*sred[tid*4+0] + pw1*sred[tid*4+1]
                      + pw2*sred[tid*4+2] + pw3*sred[tid*4+3];
            if (n0 == 0)
                rsl += pw0*g_Pb2[bin*4+0] + pw1*g_Pb2[bin*4+1]
                     + pw2*g_Pb2[bin*4+2] + pw3*g_Pb2[bin*4+3];
            atomicAdd(Out + g_perm[m0 + tid], rsl);
        }
    }
}

extern "C" void kernel_launch(void* const* d_in, const int* in_sizes, int n_in,
                              void* d_out, int out_size)
{
    const float* T  = (const float*)d_in[0];
    const float* X  = (const float*)d_in[1];
    const float* W0 = (const float*)d_in[2];
    const float* b0 = (const float*)d_in[3];
    const float* W1 = (const float*)d_in[4];
    const float* b1 = (const float*)d_in[5];
    const float* W2 = (const float*)d_in[6];
    const float* b2 = (const float*)d_in[7];
    float* out = (float*)d_out;

    int* ctrl;
    cudaGetSymbolAddress((void**)&ctrl, g_ctrl);

    cudaFuncSetAttribute(vc_fused, cudaFuncAttributeMaxDynamicSharedMemorySize, SMEM_SZ);

    cudaMemsetAsync(ctrl, 0, CTRL_WORDS * sizeof(int), 0);
    cudaMemsetAsync(out, 0, NROWS * sizeof(float), 0);
    setup_all<<<2116, 256>>>(T, W0, b0, W1, b1, W2, b2);
    vc_fused<<<2 * GEMM1_BLOCKS, 256, SMEM_SZ>>>(X, out);
}